// round 17
// baseline (speedup 1.0000x reference)
#include <cuda_runtime.h>

#define B_   32
#define IN_  2048
#define DK   8      // Din
#define N_   64     // num output capsules
#define C_   32     // weight channels
#define DD   16     // Dout
#define IPC  (IN_/C_)   // 64 input capsules per channel
#define QB   8      // CTAs per batch pipeline
#define CPQ  (C_/QB)   // 4 channels per CTA
#define GRID (B_*QB)   // 256
#define TPB  256

typedef unsigned long long u64;

// The ONLY cross-CTA scratch: partial s contributions [b][q][n][d] (1MB)
__device__ __align__(16) float g_ps[B_*QB*N_*DD];

// ---------------------------------------------------------------------------
// packed f32x2 helpers (sm_103a: FFMA2/FADD2 only reachable via PTX)
// ---------------------------------------------------------------------------
__device__ __forceinline__ u64 fma2(u64 a, u64 b, u64 c) {
    u64 d; asm("fma.rn.f32x2 %0, %1, %2, %3;" : "=l"(d) : "l"(a), "l"(b), "l"(c)); return d;
}
__device__ __forceinline__ u64 mul2(u64 a, u64 b) {
    u64 d; asm("mul.rn.f32x2 %0, %1, %2;" : "=l"(d) : "l"(a), "l"(b)); return d;
}
__device__ __forceinline__ u64 add2(u64 a, u64 b) {
    u64 d; asm("add.rn.f32x2 %0, %1, %2;" : "=l"(d) : "l"(a), "l"(b)); return d;
}
__device__ __forceinline__ u64 pack2(float lo, float hi) {
    u64 d; asm("mov.b64 %0, {%1, %2};" : "=l"(d) : "f"(lo), "f"(hi)); return d;
}
__device__ __forceinline__ float2 unpack2(u64 v) {
    float lo, hi; asm("mov.b64 {%0, %1}, %2;" : "=f"(lo), "=f"(hi) : "l"(v));
    return make_float2(lo, hi);
}
__device__ __forceinline__ float hadd2(u64 v) {
    float2 f = unpack2(v); return f.x + f.y;
}

// ---------------------------------------------------------------------------
// Per-b barrier: 32 pipelines x 8 CTA arrivals, monotonic counters (no resets
// -> deterministic across graph replays). acq_rel arrival carries every
// arriving CTA's writes into the release. 256B padding -> distinct L2 slices.
// ---------------------------------------------------------------------------
__device__ unsigned b_cnt[B_*64];
__device__ unsigned b_gen[B_*64];

__device__ __forceinline__ unsigned atom_add_ar(unsigned* p, unsigned v) {
    unsigned old;
    asm volatile("atom.add.acq_rel.gpu.u32 %0, [%1], %2;" : "=r"(old) : "l"(p), "r"(v) : "memory");
    return old;
}
__device__ __forceinline__ unsigned ld_acq(const unsigned* p) {
    unsigned v;
    asm volatile("ld.acquire.gpu.u32 %0, [%1];" : "=r"(v) : "l"(p) : "memory");
    return v;
}
__device__ __forceinline__ void st_rel(unsigned* p, unsigned v) {
    asm volatile("st.release.gpu.u32 [%0], %1;" :: "l"(p), "r"(v) : "memory");
}

__device__ __forceinline__ void b_sync(int b) {
    __syncthreads();
    if (threadIdx.x == 0) {
        unsigned* gp = &b_gen[b*64];
        unsigned gen = ld_acq(gp);
        if ((atom_add_ar(&b_cnt[b*64], 1u) & (QB-1u)) == QB-1u) {
            st_rel(gp, gen + 1u);
        } else {
            while (ld_acq(gp) == gen) __nanosleep(20);
        }
    }
    __syncthreads();
}

// ---------------------------------------------------------------------------
// partial_s: g_ps[b][q][n][d] = sum_{c in CTA, k} W[n,c,d,k] * yrow[c][n?,k]
// S0: yrow = Xs[c][:] (n-independent), scaled 1/64.  else yrow = ysum[c][n][:].
// thread t: n = t>>2, d-quad dq = t&3.
// ---------------------------------------------------------------------------
template<bool S0>
__device__ __forceinline__ void partial_s(const float* __restrict__ W,
                                          const float* Xs, const float* ysum,
                                          int b, int q) {
    int t = threadIdx.x;
    int n = t >> 2, dq = t & 3;
    u64 a0 = 0, a1 = 0, a2 = 0, a3 = 0;   // one per d in the quad
    #pragma unroll
    for (int c = 0; c < CPQ; ++c) {
        int cg = q*CPQ + c;
        const u64* yr = S0 ? (const u64*)(Xs + c*DK)
                           : (const u64*)(ysum + (c*N_ + n)*DK);
        u64 y0 = yr[0], y1 = yr[1], y2 = yr[2], y3 = yr[3];
        const ulonglong2* Wr = (const ulonglong2*)
            (W + ((size_t)n*C_ + cg)*DD*DK + dq*4*DK);
        ulonglong2 wa, wb; u64 v;
        wa = Wr[0]; wb = Wr[1];
        v = fma2(wa.x, y0, fma2(wa.y, y1, fma2(wb.x, y2, mul2(wb.y, y3)))); a0 = add2(a0, v);
        wa = Wr[2]; wb = Wr[3];
        v = fma2(wa.x, y0, fma2(wa.y, y1, fma2(wb.x, y2, mul2(wb.y, y3)))); a1 = add2(a1, v);
        wa = Wr[4]; wb = Wr[5];
        v = fma2(wa.x, y0, fma2(wa.y, y1, fma2(wb.x, y2, mul2(wb.y, y3)))); a2 = add2(a2, v);
        wa = Wr[6]; wb = Wr[7];
        v = fma2(wa.x, y0, fma2(wa.y, y1, fma2(wb.x, y2, mul2(wb.y, y3)))); a3 = add2(a3, v);
    }
    float4 s4 = make_float4(hadd2(a0), hadd2(a1), hadd2(a2), hadd2(a3));
    if (S0) { s4.x *= (1.f/64.f); s4.y *= (1.f/64.f); s4.z *= (1.f/64.f); s4.w *= (1.f/64.f); }
    *(float4*)&g_ps[(((size_t)b*QB + q)*N_ + n)*DD + dq*4] = s4;
}

// ---------------------------------------------------------------------------
// o_compute: s[n,d] = bias + sum_q g_ps[b][q][n][d]; o = squash(s).
// thread t: n = t>>2, dq = t&3; per-n reduce via 2 shfls (lanes t^1, t^2 share n).
// FINAL: write output (q==0 CTA only calls). else: o -> o_s ([dq][n] float4).
// ---------------------------------------------------------------------------
template<bool FINAL>
__device__ __forceinline__ void o_compute(const float* __restrict__ bias,
                                          float* __restrict__ out,
                                          float* o_s, int b, int q) {
    int t = threadIdx.x;
    int n = t >> 2, dq = t & 3;
    float4 s4 = *(const float4*)(bias + n*DD + dq*4);
    #pragma unroll
    for (int q2 = 0; q2 < QB; ++q2) {
        float4 p = __ldcg((const float4*)&g_ps[(((size_t)b*QB + q2)*N_ + n)*DD + dq*4]);
        s4.x += p.x; s4.y += p.y; s4.z += p.z; s4.w += p.w;
    }
    float ss = s4.x*s4.x + s4.y*s4.y + s4.z*s4.z + s4.w*s4.w;
    ss += __shfl_xor_sync(0xffffffffu, ss, 1);
    ss += __shfl_xor_sync(0xffffffffu, ss, 2);
    float scale = ss / (1.f + ss) * rsqrtf(ss + 1e-7f);
    float4 o4 = make_float4(scale*s4.x, scale*s4.y, scale*s4.z, scale*s4.w);
    if (FINAL) {
        *(float4*)&out[((size_t)b*N_ + n)*DD + dq*4] = o4;
    } else {
        ((float4*)o_s)[dq*64 + n] = o4;
    }
}

// ---------------------------------------------------------------------------
// U_update: Ul[c][n][k] (+)= sum_d o[n,d] * W[n,cg,d,k]   (CTA-local U!)
// thread t: c = t>>6 (0..3), n = t&63.
// ---------------------------------------------------------------------------
template<bool ACCUM>
__device__ __forceinline__ void U_update(const float* __restrict__ W,
                                         const float* o_s, float* Ul, int q) {
    int t = threadIdx.x;
    int c = t >> 6, n = t & 63;
    int cg = q*CPQ + c;
    // o row for this n: 16 floats as 4 float4 from [dq][n] layout
    float4 ov0 = ((const float4*)o_s)[0*64 + n];
    float4 ov1 = ((const float4*)o_s)[1*64 + n];
    float4 ov2 = ((const float4*)o_s)[2*64 + n];
    float4 ov3 = ((const float4*)o_s)[3*64 + n];
    float o_r[16] = {ov0.x,ov0.y,ov0.z,ov0.w, ov1.x,ov1.y,ov1.z,ov1.w,
                     ov2.x,ov2.y,ov2.z,ov2.w, ov3.x,ov3.y,ov3.z,ov3.w};
    const ulonglong2* Wr = (const ulonglong2*)(W + ((size_t)n*C_ + cg)*DD*DK);
    u64 a0 = 0, a1 = 0, a2 = 0, a3 = 0;   // k-pairs 0..3
    #pragma unroll
    for (int d = 0; d < DD; ++d) {
        ulonglong2 wa = Wr[d*2], wb = Wr[d*2 + 1];
        u64 op = pack2(o_r[d], o_r[d]);
        a0 = fma2(op, wa.x, a0); a1 = fma2(op, wa.y, a1);
        a2 = fma2(op, wb.x, a2); a3 = fma2(op, wb.y, a3);
    }
    u64* Ud = (u64*)(Ul + (c*N_ + n)*DK);
    if (ACCUM) {
        Ud[0] = add2(Ud[0], a0); Ud[1] = add2(Ud[1], a1);
        Ud[2] = add2(Ud[2], a2); Ud[3] = add2(Ud[3], a3);
    } else {
        Ud[0] = a0; Ud[1] = a1; Ud[2] = a2; Ud[3] = a3;
    }
}

// ---------------------------------------------------------------------------
// route: 4 channels, 2 warps/channel (cl = w>>1, hw = w&1 -> 32 capsules).
// lane l handles n0=l, n1=l+32: logits = Ul.x (packed), softmax over 64 n
// (warp butterfly), packed partial y, 2-warp combine -> ysum (ALL in smem).
// ---------------------------------------------------------------------------
__device__ __forceinline__ void route(const float* xs, const float* Ul,
                                      float* ybuf, float* ysum) {
    int t = threadIdx.x;
    int w = t >> 5, l = t & 31;
    int cl = w >> 1, hw = w & 1;

    const ulonglong2* Ub = (const ulonglong2*)(Ul + (cl*N_)*DK);
    ulonglong2 U0a = Ub[l*2],        U0b = Ub[l*2 + 1];
    ulonglong2 U1a = Ub[(l+32)*2],   U1b = Ub[(l+32)*2 + 1];
    u64 u00 = U0a.x, u01 = U0a.y, u02 = U0b.x, u03 = U0b.y;
    u64 u10 = U1a.x, u11 = U1a.y, u12 = U1b.x, u13 = U1b.y;

    u64 y00 = 0, y01 = 0, y02 = 0, y03 = 0;
    u64 y10 = 0, y11 = 0, y12 = 0, y13 = 0;

    const ulonglong2* xw2 = (const ulonglong2*)xs + (cl*IPC + hw*32)*2;
    #pragma unroll 4
    for (int i = 0; i < 32; ++i) {
        ulonglong2 xa = xw2[i*2], xb = xw2[i*2 + 1];
        u64 a0 = fma2(u00, xa.x, fma2(u01, xa.y, fma2(u02, xb.x, mul2(u03, xb.y))));
        u64 a1 = fma2(u10, xa.x, fma2(u11, xa.y, fma2(u12, xb.x, mul2(u13, xb.y))));
        float2 f0 = unpack2(a0), f1 = unpack2(a1);
        float l0 = f0.x + f0.y, l1 = f1.x + f1.y;
        float e0 = __expf(l0), e1 = __expf(l1);   // |logit| small: no max-sub
        float ts = e0 + e1;
        #pragma unroll
        for (int off = 1; off < 32; off <<= 1) ts += __shfl_xor_sync(0xffffffffu, ts, off);
        float inv = __fdividef(1.f, ts);
        u64 c0p = pack2(e0*inv, e0*inv);
        u64 c1p = pack2(e1*inv, e1*inv);
        y00 = fma2(c0p, xa.x, y00); y01 = fma2(c0p, xa.y, y01);
        y02 = fma2(c0p, xb.x, y02); y03 = fma2(c0p, xb.y, y03);
        y10 = fma2(c1p, xa.x, y10); y11 = fma2(c1p, xa.y, y11);
        y12 = fma2(c1p, xb.x, y12); y13 = fma2(c1p, xb.y, y13);
    }

    ulonglong2* yb2 = (ulonglong2*)ybuf + w * 128;
    yb2[l*2]          = make_ulonglong2(y00, y01);
    yb2[l*2 + 1]      = make_ulonglong2(y02, y03);
    yb2[(l+32)*2]     = make_ulonglong2(y10, y11);
    yb2[(l+32)*2 + 1] = make_ulonglong2(y12, y13);
    __syncthreads();

    // 2-warp combine: thread t -> channel ch = t>>6, slots s0 and s0+64
    ulonglong2* yb = (ulonglong2*)ybuf;
    int ch = t >> 6, s0 = t & 63;
    #pragma unroll
    for (int r = 0; r < 2; ++r) {
        int slot = s0 + r*64;
        ulonglong2 p0 = yb[(ch*2    )*128 + slot];
        ulonglong2 p1 = yb[(ch*2 + 1)*128 + slot];
        int n = slot >> 1, hf = slot & 1;
        ((ulonglong2*)ysum)[(ch*N_ + n)*2 + hf] =
            make_ulonglong2(add2(p0.x, p1.x), add2(p0.y, p1.y));
    }
}

// ---------------------------------------------------------------------------
// Fused kernel: grid 256x256 = 32 b-pipelines x 8 CTAs. Only THREE global
// barriers; U and y are CTA-local (smem); only partial-s crosses CTAs.
// ---------------------------------------------------------------------------
__global__ void __launch_bounds__(TPB) fused_kernel(
        const float* __restrict__ x, const float* __restrict__ W,
        const float* __restrict__ bias, float* __restrict__ out) {
    __shared__ __align__(16) float xs[CPQ*IPC*DK];   // 8KB  x tile (own channels)
    __shared__ __align__(16) float Xs[CPQ*DK];       // 128B per-channel x sums
    __shared__ __align__(16) float Ul[CPQ*N_*DK];    // 8KB  CTA-local U
    __shared__ __align__(16) float o_s[N_*DD];       // 4KB  squashed outputs
    __shared__ __align__(16) float ybuf[8*N_*DK];    // 16KB per-warp y partials
    __shared__ __align__(16) float ysum[CPQ*N_*DK];  // 8KB  combined y

    int b = blockIdx.x >> 3;
    int q = blockIdx.x & (QB-1);
    int t = threadIdx.x;

    // ---- P0: stage x, per-channel sums Xs, partial_s0 ----
    {
        const float4* xg = (const float4*)(x + (size_t)(b*IN_ + q*CPQ*IPC) * DK);
        float4* xs4 = (float4*)xs;
        xs4[t]       = xg[t];
        xs4[t + 256] = xg[t + 256];
    }
    __syncthreads();
    {   // Xs[c*8+k] = sum_i xs[c][i][k]; 8 threads per output
        int outi = t >> 3, sub = t & 7;
        int c = outi >> 3, k = outi & 7;
        const float* xp = xs + c*IPC*DK + sub*8*DK + k;
        float s = 0.f;
        #pragma unroll
        for (int j = 0; j < 8; ++j) s += xp[j*DK];
        s += __shfl_xor_sync(0xffffffffu, s, 1);
        s += __shfl_xor_sync(0xffffffffu, s, 2);
        s += __shfl_xor_sync(0xffffffffu, s, 4);
        if (sub == 0) Xs[outi] = s;
    }
    __syncthreads();
    partial_s<true>(W, Xs, ysum, b, q);
    b_sync(b);

    // ---- ITER 1 ----
    o_compute<false>(bias, out, o_s, b, q);
    __syncthreads();
    U_update<false>(W, o_s, Ul, q);      // U = o0^T W
    __syncthreads();
    route(xs, Ul, ybuf, ysum);
    __syncthreads();
    partial_s<false>(W, Xs, ysum, b, q);
    b_sync(b);

    // ---- ITER 2 ----
    o_compute<false>(bias, out, o_s, b, q);
    __syncthreads();
    U_update<true>(W, o_s, Ul, q);       // U += o1^T W
    __syncthreads();
    route(xs, Ul, ybuf, ysum);
    __syncthreads();
    partial_s<false>(W, Xs, ysum, b, q);
    b_sync(b);

    // ---- FINAL: squash -> output (one CTA per b-group writes) ----
    if (q == 0) o_compute<true>(bias, out, o_s, b, q);
}

// ---------------------------------------------------------------------------
extern "C" void kernel_launch(void* const* d_in, const int* in_sizes, int n_in,
                              void* d_out, int out_size) {
    const float* x    = (const float*)d_in[0];   // [32, 2048, 8]
    const float* W    = (const float*)d_in[1];   // [64, 32, 16, 8]
    const float* bias = (const float*)d_in[2];   // [64, 16]
    float* out = (float*)d_out;                  // [32, 64, 16]

    fused_kernel<<<GRID, TPB>>>(x, W, bias, out);
}